// round 1
// baseline (speedup 1.0000x reference)
#include <cuda_runtime.h>
#include <math.h>

// Net_ASAP: fused per-graph pipeline. One CTA per graph (G=512), 256 threads.
// All per-graph state lives in shared memory; weights staged through a SMEM
// transpose tile. fp32 throughout (top-k is selection-sensitive).

#define G_TOT 512
#define SLOPE 0.2f

#define LDA 132   // feature buffers: 64 rows x 128 (+4 pad)
#define LDJ 66    // adjacency / attention: 64 x 64 (+2 pad, keeps float2 alignment)
#define LDW 132   // transposed weight tile: 128 x 128 (+4 pad)

struct Smem {
  float A [64*LDA];
  float B [64*LDA];
  float Cb[64*LDA];
  float ADJ[64*LDJ];
  float S  [64*LDJ];
  float WT [128*LDW];
  float cnt[64];
  float degw[64];
  float s1[64];
  float s2[64];
  float fit[64];
  float av[64];
  float bv[64];
  float cv[64];
  float vals[64];
  int   perm[64];
  float xsum[5*128];
  float adjn[16*17];
  float zz[128];
  float yy[16];
  float red[64];
};

// ---------------------------------------------------------------------------
// helpers
// ---------------------------------------------------------------------------

// Load a [128 x 128] row-major global weight W[h][f] transposed into smem
// WT[f*LDW + h]. Coalesced global reads.
__device__ __forceinline__ void load_wt(float* WT, const float* __restrict__ Wg, int tid)
{
  for (int idx = tid; idx < 128*128; idx += 256) {
    int h = idx >> 7, f = idx & 127;
    WT[f*LDW + h] = Wg[idx];
  }
}

// Core GEMM accumulate: acc[r][c] (+)= sum_k L[(i0+r)*ldl + k] * R[k*ldr + hb + col(c)]
// Column mapping: columns handled by this thread are hb + 32*j + e (j<4, e<2),
// hb = 2*(tid&15). R rows must be 8B-aligned at even offsets (all ld* are even).
template<int RI, bool ZERO>
__device__ __forceinline__ void mm_acc(float (&acc)[RI][8],
    const float* __restrict__ L, int ldl,
    const float* __restrict__ R, int ldr,
    int i0, int hb, int K)
{
  if (ZERO) {
#pragma unroll
    for (int r = 0; r < RI; r++)
#pragma unroll
      for (int c = 0; c < 8; c++) acc[r][c] = 0.f;
  }
#pragma unroll 2
  for (int k = 0; k < K; k++) {
    float2 rv[4];
    const float* Rp = R + k*ldr + hb;
#pragma unroll
    for (int j = 0; j < 4; j++) rv[j] = *reinterpret_cast<const float2*>(Rp + 32*j);
#pragma unroll
    for (int r = 0; r < RI; r++) {
      float lv = L[(i0+r)*ldl + k];
#pragma unroll
      for (int j = 0; j < 4; j++) {
        acc[r][2*j  ] = fmaf(lv, rv[j].x, acc[r][2*j  ]);
        acc[r][2*j+1] = fmaf(lv, rv[j].y, acc[r][2*j+1]);
      }
    }
  }
}

// Masked max-aggregation: acc[r][c] = max over k with Adj[i0+r][k]!=0 of X[k][col]
template<int RI>
__device__ __forceinline__ void mm_maxagg(float (&acc)[RI][8],
    const float* __restrict__ Adj,
    const float* __restrict__ X,
    int i0, int hb, int NI)
{
#pragma unroll
  for (int r = 0; r < RI; r++)
#pragma unroll
    for (int c = 0; c < 8; c++) acc[r][c] = -1e30f;
  for (int k = 0; k < NI; k++) {
    float2 rv[4];
    const float* Rp = X + k*LDA + hb;
#pragma unroll
    for (int j = 0; j < 4; j++) rv[j] = *reinterpret_cast<const float2*>(Rp + 32*j);
#pragma unroll
    for (int r = 0; r < RI; r++) {
      float a = Adj[(i0+r)*LDJ + k];
      bool m = (a != 0.f);
#pragma unroll
      for (int j = 0; j < 4; j++) {
        float v0 = fmaxf(acc[r][2*j  ], rv[j].x);
        float v1 = fmaxf(acc[r][2*j+1], rv[j].y);
        acc[r][2*j  ] = m ? v0 : acc[r][2*j  ];
        acc[r][2*j+1] = m ? v1 : acc[r][2*j+1];
      }
    }
  }
}

template<int RI>
__device__ __forceinline__ void mm_store(const float (&acc)[RI][8],
    float* O, int ldo, int i0, int hb)
{
#pragma unroll
  for (int r = 0; r < RI; r++)
#pragma unroll
    for (int j = 0; j < 4; j++)
      *reinterpret_cast<float2*>(O + (i0+r)*ldo + hb + 32*j) =
          make_float2(acc[r][2*j], acc[r][2*j+1]);
}

// ---------------------------------------------------------------------------
// graph conv: out = relu( ADJ @ (X @ wr^T) / cnt + X @ wroot^T + br )
// ---------------------------------------------------------------------------
__device__ void graph_conv(Smem* s, float** Xp, float** T1p, float** T2p,
    const float* __restrict__ wr, const float* __restrict__ br,
    const float* __restrict__ wroot, int NI, int tid)
{
  float* Xin = *Xp; float* Xt = *T1p; float* Xo = *T2p;
  const int ti = tid >> 4, th = tid & 15, hb = th * 2;

  if (tid < NI) {
    const float* row = s->ADJ + tid*LDJ;
    int c = 0;
    for (int j = 0; j < NI; j++) c += (row[j] != 0.f) ? 1 : 0;
    s->cnt[tid] = (c > 0) ? (float)c : 1.f;
  }
  load_wt(s->WT, wr, tid);
  __syncthreads();

  // Xt = Xin @ WT
  if (NI == 64) {
    float acc[4][8];
    mm_acc<4, true>(acc, Xin, LDA, s->WT, LDW, ti*4, hb, 128);
    mm_store<4>(acc, Xt, LDA, ti*4, hb);
  } else if (ti < NI) {
    float acc[1][8];
    mm_acc<1, true>(acc, Xin, LDA, s->WT, LDW, ti, hb, 128);
    mm_store<1>(acc, Xt, LDA, ti, hb);
  }
  __syncthreads();

  load_wt(s->WT, wroot, tid);
  __syncthreads();

  float2 bb[4];
#pragma unroll
  for (int j = 0; j < 4; j++) bb[j] = *reinterpret_cast<const float2*>(br + hb + 32*j);

  if (NI == 64) {
    float acc[4][8];
    mm_acc<4, true>(acc, s->ADJ, LDJ, Xt, LDA, ti*4, hb, NI);
#pragma unroll
    for (int r = 0; r < 4; r++) {
      float rc = 1.f / s->cnt[ti*4 + r];
#pragma unroll
      for (int c = 0; c < 8; c++) acc[r][c] *= rc;
    }
    mm_acc<4, false>(acc, Xin, LDA, s->WT, LDW, ti*4, hb, 128);
#pragma unroll
    for (int r = 0; r < 4; r++)
#pragma unroll
      for (int j = 0; j < 4; j++) {
        acc[r][2*j  ] = fmaxf(acc[r][2*j  ] + bb[j].x, 0.f);
        acc[r][2*j+1] = fmaxf(acc[r][2*j+1] + bb[j].y, 0.f);
      }
    mm_store<4>(acc, Xo, LDA, ti*4, hb);
  } else if (ti < NI) {
    float acc[1][8];
    mm_acc<1, true>(acc, s->ADJ, LDJ, Xt, LDA, ti, hb, NI);
    float rc = 1.f / s->cnt[ti];
#pragma unroll
    for (int c = 0; c < 8; c++) acc[0][c] *= rc;
    mm_acc<1, false>(acc, Xin, LDA, s->WT, LDW, ti, hb, 128);
#pragma unroll
    for (int j = 0; j < 4; j++) {
      acc[0][2*j  ] = fmaxf(acc[0][2*j  ] + bb[j].x, 0.f);
      acc[0][2*j+1] = fmaxf(acc[0][2*j+1] + bb[j].y, 0.f);
    }
    mm_store<1>(acc, Xo, LDA, ti, hb);
  }
  __syncthreads();

  *Xp = Xo; *T2p = Xin;   // rotate buffers: features now in Xo
}

__device__ void mean_pool(Smem* s, const float* X, int NI, int stage, int tid)
{
  if (tid < 128) {
    float a = 0.f;
    for (int i = 0; i < NI; i++) a += X[i*LDA + tid];
    s->xsum[stage*128 + tid] = a * (1.f / (float)NI);
  }
}

// ---------------------------------------------------------------------------
// ASAP pool
// ---------------------------------------------------------------------------
__device__ void asap_pool(Smem* s, float** Xp, float** T1p, float** T2p,
    int NI, int kk,
    const float* __restrict__ lw,  const float* __restrict__ lb,
    const float* __restrict__ aw,  const float* __restrict__ abp,
    const float* __restrict__ l1w, const float* __restrict__ l1bp,
    const float* __restrict__ l2w,
    const float* __restrict__ l3w, const float* __restrict__ l3bp,
    int tid)
{
  float* X   = *Xp;
  float* XQR = *T1p;  // max-agg result, later reused as XC
  float* XQ  = *T2p;  // xq after linear, later reused as new features
  const int ti = tid >> 4, th = tid & 15, hb = th * 2;
  const float ab = abp[0];

  // 1. adj1 diagonal fix + degree (values) per row
  if (tid < NI) {
    float d = s->ADJ[tid*LDJ + tid];
    if (d == 0.f) s->ADJ[tid*LDJ + tid] = 1.f;
    float sum = 0.f;
    const float* row = s->ADJ + tid*LDJ;
    for (int j = 0; j < NI; j++) sum += row[j];
    s->degw[tid] = sum;
  }
  __syncthreads();

  // 2. xq_raw = masked neighborhood max  -> XQR ; also stage lw^T into WT
  if (NI == 64) {
    float acc[4][8];
    mm_maxagg<4>(acc, s->ADJ, X, ti*4, hb, NI);
    mm_store<4>(acc, XQR, LDA, ti*4, hb);
  } else if (ti < NI) {
    float acc[1][8];
    mm_maxagg<1>(acc, s->ADJ, X, ti, hb, NI);
    mm_store<1>(acc, XQR, LDA, ti, hb);
  }
  load_wt(s->WT, lw, tid);
  __syncthreads();

  // 3. XQ = XQR @ lw^T + lb
  {
    float2 bb[4];
#pragma unroll
    for (int j = 0; j < 4; j++) bb[j] = *reinterpret_cast<const float2*>(lb + hb + 32*j);
    if (NI == 64) {
      float acc[4][8];
      mm_acc<4, true>(acc, XQR, LDA, s->WT, LDW, ti*4, hb, 128);
#pragma unroll
      for (int r = 0; r < 4; r++)
#pragma unroll
        for (int j = 0; j < 4; j++) { acc[r][2*j] += bb[j].x; acc[r][2*j+1] += bb[j].y; }
      mm_store<4>(acc, XQ, LDA, ti*4, hb);
    } else if (ti < NI) {
      float acc[1][8];
      mm_acc<1, true>(acc, XQR, LDA, s->WT, LDW, ti, hb, 128);
#pragma unroll
      for (int j = 0; j < 4; j++) { acc[0][2*j] += bb[j].x; acc[0][2*j+1] += bb[j].y; }
      mm_store<1>(acc, XQ, LDA, ti, hb);
    }
  }
  __syncthreads();

  // 4. s1[i] = xq[i].aw[:128] ; s2[i] = x[i].aw[128:]
  if (tid < NI) {
    const float* r = XQ + tid*LDA;
    float a = 0.f;
#pragma unroll 4
    for (int h = 0; h < 128; h++) a += r[h] * aw[h];
    s->s1[tid] = a;
  } else if (tid >= 128 && tid < 128 + NI) {
    int i = tid - 128;
    const float* r = X + i*LDA;
    float a = 0.f;
#pragma unroll 4
    for (int h = 0; h < 128; h++) a += r[h] * aw[128 + h];
    s->s2[i] = a;
  }
  __syncthreads();

  // 5. masked softmax attention -> S
  {
    const int w = tid >> 5, lane = tid & 31;
    const int nch = (NI + 31) >> 5;
    for (int i = w; i < NI; i += 8) {
      float s1i = s->s1[i];
      float ev[2] = {-1e30f, -1e30f};
      float mx = -1e30f;
      for (int c = 0; c < nch; c++) {
        int j = c*32 + lane;
        float adjv = (j < NI) ? s->ADJ[i*LDJ + j] : 0.f;
        float e = s1i + ((j < NI) ? s->s2[j] : 0.f) + ab;
        e = (e > 0.f) ? e : SLOPE * e;
        ev[c] = (adjv != 0.f) ? e : -1e30f;
        mx = fmaxf(mx, ev[c]);
      }
#pragma unroll
      for (int o = 16; o; o >>= 1) mx = fmaxf(mx, __shfl_xor_sync(0xffffffffu, mx, o));
      float ex[2]; float sum = 0.f;
      for (int c = 0; c < nch; c++) {
        ex[c] = (ev[c] > -5e29f) ? __expf(ev[c] - mx) : 0.f;
        sum += ex[c];
      }
#pragma unroll
      for (int o = 16; o; o >>= 1) sum += __shfl_xor_sync(0xffffffffu, sum, o);
      float inv = 1.f / sum;
      for (int c = 0; c < nch; c++) {
        int j = c*32 + lane;
        if (j < NI) s->S[i*LDJ + j] = ex[c] * inv;
      }
    }
  }
  __syncthreads();

  // 6. XC = S @ X   (into XQR buffer)
  float* XC = XQR;
  if (NI == 64) {
    float acc[4][8];
    mm_acc<4, true>(acc, s->S, LDJ, X, LDA, ti*4, hb, NI);
    mm_store<4>(acc, XC, LDA, ti*4, hb);
  } else if (ti < NI) {
    float acc[1][8];
    mm_acc<1, true>(acc, s->S, LDJ, X, LDA, ti, hb, NI);
    mm_store<1>(acc, XC, LDA, ti, hb);
  }
  __syncthreads();

  // 7. av = XC.l1w + l1b ; bv = XC.l2w ; cv = XC.l3w + l3b
  {
    int grp = tid >> 6, idx = tid & 63;
    if (grp < 3 && idx < NI) {
      const float* w3 = (grp == 0) ? l1w : (grp == 1) ? l2w : l3w;
      const float* r = XC + idx*LDA;
      float a = 0.f;
#pragma unroll 4
      for (int h = 0; h < 128; h++) a += r[h] * w3[h];
      if (grp == 0)      s->av[idx] = a + l1bp[0];
      else if (grp == 1) s->bv[idx] = a;
      else               s->cv[idx] = a + l3bp[0];
    }
  }
  __syncthreads();

  // 8. fit = sigmoid( adj1 @ av - bv*degw + cv )
  if (tid < NI) {
    float a = 0.f;
    const float* row = s->ADJ + tid*LDJ;
    for (int j = 0; j < NI; j++) a += row[j] * s->av[j];
    float f = a - s->bv[tid]*s->degw[tid] + s->cv[tid];
    s->fit[tid] = 1.f / (1.f + expf(-f));
  }
  __syncthreads();

  // 9. top-k (strict > scan ascending matches lowest-index tie-break)
  if (tid == 0) {
    for (int t = 0; t < kk; t++) {
      float best = -1.f; int bi = 0;
      for (int i = 0; i < NI; i++) {
        float v = s->fit[i];
        if (v > best) { best = v; bi = i; }
      }
      s->perm[t] = bi; s->vals[t] = best; s->fit[bi] = -2.f;
    }
  }
  __syncthreads();

  // 10. xn = XC[perm] * vals   -> XQ buffer (new features)
  float* XN = XQ;
  for (int idx = tid; idx < kk*128; idx += 256) {
    int t = idx >> 7, h = idx & 127;
    XN[t*LDA + h] = XC[s->perm[t]*LDA + h] * s->vals[t];
  }
  // 11. T[t][m] = sum_n S[perm[t]][n] * ADJ[n][m]  -> old X buffer (dead)
  float* Tb = X;
  for (int idx = tid; idx < kk*NI; idx += 256) {
    int t = idx / NI, m = idx - t*NI;
    const float* srow = s->S + s->perm[t]*LDJ;
    float a = 0.f;
    for (int n = 0; n < NI; n++) a += srow[n] * s->ADJ[n*LDJ + m];
    Tb[t*LDA + m] = a;
  }
  __syncthreads();

  // 12. adjn[t][l] = sum_m T[t][m]*S[perm[l]][m], zero diagonal
  for (int idx = tid; idx < kk*kk; idx += 256) {
    int t = idx / kk, l = idx - t*kk;
    const float* sl = s->S + s->perm[l]*LDJ;
    const float* tr = Tb + t*LDA;
    float a = 0.f;
    for (int m = 0; m < NI; m++) a += tr[m] * sl[m];
    s->adjn[t*17 + l] = (t == l) ? 0.f : a;
  }
  __syncthreads();
  for (int idx = tid; idx < kk*kk; idx += 256) {
    int t = idx / kk, l = idx - t*kk;
    s->ADJ[t*LDJ + l] = s->adjn[t*17 + l];
  }
  __syncthreads();

  *Xp = XN; *T2p = X;   // features now in XN; old X becomes scratch
}

// ---------------------------------------------------------------------------
// main kernel
// ---------------------------------------------------------------------------
__global__ void __launch_bounds__(256, 1) asap_kernel(
    const float* __restrict__ x,          const float* __restrict__ adj,
    const float* __restrict__ conv1_wr,   const float* __restrict__ conv1_br,
    const float* __restrict__ conv1_wroot,
    const float* __restrict__ convs_wr,   const float* __restrict__ convs_br,
    const float* __restrict__ convs_wroot,
    const float* __restrict__ pool_lin_w, const float* __restrict__ pool_lin_b,
    const float* __restrict__ pool_att_w, const float* __restrict__ pool_att_b,
    const float* __restrict__ pool_le1_w, const float* __restrict__ pool_le1_b,
    const float* __restrict__ pool_le2_w,
    const float* __restrict__ pool_le3_w, const float* __restrict__ pool_le3_b,
    const float* __restrict__ lin1_w,     const float* __restrict__ lin1_b,
    const float* __restrict__ lin2_w,     const float* __restrict__ lin2_b,
    float* __restrict__ out)
{
  extern __shared__ unsigned char smraw[];
  Smem* s = reinterpret_cast<Smem*>(smraw);
  const int g = blockIdx.x, tid = threadIdx.x;

  for (int idx = tid; idx < 64*128; idx += 256)
    s->A[(idx >> 7)*LDA + (idx & 127)] = x[g*(64*128) + idx];
  for (int idx = tid; idx < 64*64; idx += 256)
    s->ADJ[(idx >> 6)*LDJ + (idx & 63)] = adj[g*(64*64) + idx];
  __syncthreads();

  float* X  = s->A;
  float* T1 = s->B;
  float* T2 = s->Cb;
  int NI = 64;

  graph_conv(s, &X, &T1, &T2, conv1_wr, conv1_br, conv1_wroot, NI, tid);
  mean_pool(s, X, NI, 0, tid);

  for (int i = 0; i < 4; i++) {
    graph_conv(s, &X, &T1, &T2, convs_wr + i*16384, convs_br + i*128,
               convs_wroot + i*16384, NI, tid);
    mean_pool(s, X, NI, i + 1, tid);
    if (i == 0 || i == 2) {
      int p = i >> 1;
      int kk = (p == 0) ? 16 : 4;
      asap_pool(s, &X, &T1, &T2, NI, kk,
                pool_lin_w + p*16384, pool_lin_b + p*128,
                pool_att_w + p*256,  pool_att_b + p,
                pool_le1_w + p*128,  pool_le1_b + p,
                pool_le2_w + p*128,
                pool_le3_w + p*128,  pool_le3_b + p, tid);
      NI = kk;
    }
  }
  __syncthreads();

  // MLP head: z = concat(xsum[0..4]) [640] ; zz = relu(z @ lin1_w^T + lin1_b)
  if (tid < 128) {
    float a = lin1_b[tid];
    const float* wrow = lin1_w + tid*640;
#pragma unroll 4
    for (int k = 0; k < 640; k++) a += s->xsum[k] * wrow[k];
    s->zz[tid] = fmaxf(a, 0.f);
  }
  __syncthreads();
  if (tid < 10) {
    float a = lin2_b[tid];
    const float* wrow = lin2_w + tid*128;
#pragma unroll 4
    for (int k = 0; k < 128; k++) a += s->zz[k] * wrow[k];
    s->yy[tid] = a;
  }
  __syncthreads();
  if (tid == 0) {
    float mx = -1e30f;
    for (int c = 0; c < 10; c++) mx = fmaxf(mx, s->yy[c]);
    float sum = 0.f;
    for (int c = 0; c < 10; c++) sum += expf(s->yy[c] - mx);
    s->red[0] = mx + logf(sum);
  }
  __syncthreads();
  if (tid < 10) out[g*10 + tid] = s->yy[tid] - s->red[0];
}

// ---------------------------------------------------------------------------
// launch
// ---------------------------------------------------------------------------
extern "C" void kernel_launch(void* const* d_in, const int* in_sizes, int n_in,
                              void* d_out, int out_size)
{
  const float* x           = (const float*)d_in[0];
  const float* adj         = (const float*)d_in[1];
  const float* conv1_wr    = (const float*)d_in[2];
  const float* conv1_br    = (const float*)d_in[3];
  const float* conv1_wroot = (const float*)d_in[4];
  const float* convs_wr    = (const float*)d_in[5];
  const float* convs_br    = (const float*)d_in[6];
  const float* convs_wroot = (const float*)d_in[7];
  const float* pool_lin_w  = (const float*)d_in[8];
  const float* pool_lin_b  = (const float*)d_in[9];
  const float* pool_att_w  = (const float*)d_in[10];
  const float* pool_att_b  = (const float*)d_in[11];
  const float* pool_le1_w  = (const float*)d_in[12];
  const float* pool_le1_b  = (const float*)d_in[13];
  const float* pool_le2_w  = (const float*)d_in[14];
  const float* pool_le3_w  = (const float*)d_in[15];
  const float* pool_le3_b  = (const float*)d_in[16];
  const float* lin1_w      = (const float*)d_in[17];
  const float* lin1_b      = (const float*)d_in[18];
  const float* lin2_w      = (const float*)d_in[19];
  const float* lin2_b      = (const float*)d_in[20];
  float* out = (float*)d_out;

  cudaFuncSetAttribute(asap_kernel, cudaFuncAttributeMaxDynamicSharedMemorySize,
                       (int)sizeof(Smem));
  asap_kernel<<<G_TOT, 256, sizeof(Smem)>>>(
      x, adj, conv1_wr, conv1_br, conv1_wroot,
      convs_wr, convs_br, convs_wroot,
      pool_lin_w, pool_lin_b, pool_att_w, pool_att_b,
      pool_le1_w, pool_le1_b, pool_le2_w, pool_le3_w, pool_le3_b,
      lin1_w, lin1_b, lin2_w, lin2_b, out);
}

// round 2
// speedup vs baseline: 1.6261x; 1.6261x over previous
#include <cuda_runtime.h>
#include <math.h>

// Net_ASAP fused pipeline, round 2.
// - One CTA per graph (G=512), 512 threads, ~207KB dynamic smem.
// - Packed f32x2 FMA (Blackwell) in all dense GEMMs.
// - float4-vectorized smem GEMM operands; weights pre-transposed into a
//   __device__ global by a prologue kernel (conflict-free float4 staging).
// - Zero-skip on adjacency-operand GEMMs (~75% sparse).
// - Warp-parallel dots / argmax-topk / reductions for all small stages.

#define THREADS 512
#define G_TOT 512
#define SLOPE 0.2f
#define LDA 128
#define LDJ 68
#define LDW 128

typedef unsigned long long u64;

__device__ float g_WT[12 * 128 * 128];   // pre-transposed weights W^T[f][h]

// ---------------------------------------------------------------------------
// packed f32x2 helpers
// ---------------------------------------------------------------------------
__device__ __forceinline__ u64 bcast2(float v) {
  unsigned r = __float_as_uint(v);
  u64 d;
  asm("mov.b64 %0, {%1, %1};" : "=l"(d) : "r"(r));
  return d;
}
__device__ __forceinline__ u64 ffma2(u64 a, u64 b, u64 c) {
  u64 d;
  asm("fma.rn.f32x2 %0, %1, %2, %3;" : "=l"(d) : "l"(a), "l"(b), "l"(c));
  return d;
}
__device__ __forceinline__ u64 fmul2(u64 a, u64 b) {
  u64 d;
  asm("mul.rn.f32x2 %0, %1, %2;" : "=l"(d) : "l"(a), "l"(b));
  return d;
}

union V4 { float4 f; u64 p[2]; float s[4]; };

struct Smem {
  float A[64 * LDA];
  float B[64 * LDA];
  float Cb[64 * LDA];
  float ADJ[64 * LDJ];
  float S[64 * LDJ];
  float WT[128 * LDW];
  float part[512];
  float cnt[64], degw[64], s1[64], s2[64], fit[64];
  float av[64], bv[64], cv[64], vals[64];
  int   perm[64];
  float xsum[640];
  float adjn[256];
  float zz[128];
  float yy[16];
  float lse;
};

// ---------------------------------------------------------------------------
// GEMM core: acc[r][p] accumulates f32x2 pairs of
//   sum_k L[(i0+r)*ldl + k] * R[k*ldr + col]   cols = c0..c0+3, c0+64..c0+67
// SKIPZ: skip k when all row multipliers are zero (adjacency operands).
// ---------------------------------------------------------------------------
template<int RI, bool SKIPZ>
__device__ __forceinline__ void mm2(u64 (&acc)[RI][4],
    const float* __restrict__ L, int ldl,
    const float* __restrict__ R, int ldr,
    int i0, int c0, int K)
{
#pragma unroll 2
  for (int k = 0; k < K; k += 4) {
    V4 lv[RI];
#pragma unroll
    for (int r = 0; r < RI; r++)
      lv[r].f = *reinterpret_cast<const float4*>(L + (i0 + r) * ldl + k);
    const float* Rp = R + k * ldr + c0;
#pragma unroll
    for (int q = 0; q < 4; q++) {
      float l0 = lv[0].s[q];
      float l1 = 0.f;
      if constexpr (RI > 1) l1 = lv[1].s[q];
      if (SKIPZ) {
        bool any = (l0 != 0.f);
        if constexpr (RI > 1) any = any || (l1 != 0.f);
        if (!any) continue;
      }
      V4 ra, rb;
      ra.f = *reinterpret_cast<const float4*>(Rp + q * ldr);
      rb.f = *reinterpret_cast<const float4*>(Rp + q * ldr + 64);
      if (!SKIPZ || l0 != 0.f) {
        u64 lp = bcast2(l0);
        acc[0][0] = ffma2(lp, ra.p[0], acc[0][0]);
        acc[0][1] = ffma2(lp, ra.p[1], acc[0][1]);
        acc[0][2] = ffma2(lp, rb.p[0], acc[0][2]);
        acc[0][3] = ffma2(lp, rb.p[1], acc[0][3]);
      }
      if constexpr (RI > 1) {
        if (!SKIPZ || l1 != 0.f) {
          u64 lp = bcast2(l1);
          acc[1][0] = ffma2(lp, ra.p[0], acc[1][0]);
          acc[1][1] = ffma2(lp, ra.p[1], acc[1][1]);
          acc[1][2] = ffma2(lp, rb.p[0], acc[1][2]);
          acc[1][3] = ffma2(lp, rb.p[1], acc[1][3]);
        }
      }
    }
  }
}

template<int RI>
__device__ __forceinline__ void mm_zero(u64 (&acc)[RI][4]) {
#pragma unroll
  for (int r = 0; r < RI; r++)
#pragma unroll
    for (int j = 0; j < 4; j++) acc[r][j] = 0ull;
}

template<int RI>
__device__ __forceinline__ void mm_store(const u64 (&acc)[RI][4],
    float* O, int ldo, int i0, int c0)
{
#pragma unroll
  for (int r = 0; r < RI; r++) {
    V4 a, b;
    a.p[0] = acc[r][0]; a.p[1] = acc[r][1];
    b.p[0] = acc[r][2]; b.p[1] = acc[r][3];
    *reinterpret_cast<float4*>(O + (i0 + r) * ldo + c0)      = a.f;
    *reinterpret_cast<float4*>(O + (i0 + r) * ldo + c0 + 64) = b.f;
  }
}

// epilogue: (+bias, relu) then store
template<int RI, bool RELU>
__device__ __forceinline__ void mm_epi_store(const u64 (&acc)[RI][4],
    const float4 b1, const float4 b2, float* O, int ldo, int i0, int c0)
{
#pragma unroll
  for (int r = 0; r < RI; r++) {
    V4 a, b;
    a.p[0] = acc[r][0]; a.p[1] = acc[r][1];
    b.p[0] = acc[r][2]; b.p[1] = acc[r][3];
    a.f.x += b1.x; a.f.y += b1.y; a.f.z += b1.z; a.f.w += b1.w;
    b.f.x += b2.x; b.f.y += b2.y; b.f.z += b2.z; b.f.w += b2.w;
    if (RELU) {
      a.f.x = fmaxf(a.f.x, 0.f); a.f.y = fmaxf(a.f.y, 0.f);
      a.f.z = fmaxf(a.f.z, 0.f); a.f.w = fmaxf(a.f.w, 0.f);
      b.f.x = fmaxf(b.f.x, 0.f); b.f.y = fmaxf(b.f.y, 0.f);
      b.f.z = fmaxf(b.f.z, 0.f); b.f.w = fmaxf(b.f.w, 0.f);
    }
    *reinterpret_cast<float4*>(O + (i0 + r) * ldo + c0)      = a.f;
    *reinterpret_cast<float4*>(O + (i0 + r) * ldo + c0 + 64) = b.f;
  }
}

// masked max aggregation (scalar fmax, branch-skips zero adj entries)
template<int RI>
__device__ __forceinline__ void mm_maxagg(float (&acc)[RI][8],
    const float* __restrict__ Adj, const float* __restrict__ X,
    int i0, int c0, int NI)
{
#pragma unroll
  for (int r = 0; r < RI; r++)
#pragma unroll
    for (int c = 0; c < 8; c++) acc[r][c] = -1e30f;
  for (int k = 0; k < NI; k += 4) {
    V4 av[RI];
#pragma unroll
    for (int r = 0; r < RI; r++)
      av[r].f = *reinterpret_cast<const float4*>(Adj + (i0 + r) * LDJ + k);
#pragma unroll
    for (int q = 0; q < 4; q++) {
      bool any = (av[0].s[q] != 0.f);
      if constexpr (RI > 1) any = any || (av[1].s[q] != 0.f);
      if (!any) continue;
      V4 ra, rb;
      ra.f = *reinterpret_cast<const float4*>(X + (k + q) * LDA + c0);
      rb.f = *reinterpret_cast<const float4*>(X + (k + q) * LDA + c0 + 64);
#pragma unroll
      for (int r = 0; r < RI; r++) {
        float m = (r == 0) ? av[0].s[q] : av[RI - 1].s[q];
        if (m != 0.f) {
          acc[r][0] = fmaxf(acc[r][0], ra.s[0]);
          acc[r][1] = fmaxf(acc[r][1], ra.s[1]);
          acc[r][2] = fmaxf(acc[r][2], ra.s[2]);
          acc[r][3] = fmaxf(acc[r][3], ra.s[3]);
          acc[r][4] = fmaxf(acc[r][4], rb.s[0]);
          acc[r][5] = fmaxf(acc[r][5], rb.s[1]);
          acc[r][6] = fmaxf(acc[r][6], rb.s[2]);
          acc[r][7] = fmaxf(acc[r][7], rb.s[3]);
        }
      }
    }
  }
}

// ---------------------------------------------------------------------------
// small helpers
// ---------------------------------------------------------------------------
__device__ __forceinline__ void load_wt(float* WT, int widx, int tid) {
  const float4* src = reinterpret_cast<const float4*>(g_WT + widx * 16384);
  float4* dst = reinterpret_cast<float4*>(WT);
#pragma unroll
  for (int i = 0; i < 8; i++) dst[tid + i * 512] = src[tid + i * 512];
}

__device__ __forceinline__ float warp_red_sum(float v) {
#pragma unroll
  for (int o = 16; o; o >>= 1) v += __shfl_xor_sync(0xffffffffu, v, o);
  return v;
}

// ---------------------------------------------------------------------------
// graph conv: out = relu( ADJ @ (X @ wr^T) / cnt + X @ wroot^T + br )
// ---------------------------------------------------------------------------
template<int NI>
__device__ void graph_conv(Smem* s, float** Xp, float** T1p, float** T2p,
    int widx_r, int widx_root, const float* __restrict__ br, int tid)
{
  float* X  = *Xp;
  float* T1 = *T1p;
  float* T2 = *T2p;
  constexpr int RI = (NI == 64) ? 2 : 1;
  const int ti = tid >> 4, th = tid & 15, c0 = th * 4;
  const int i0 = (NI == 64) ? ti * 2 : ti;
  const bool act = (NI == 64) || (ti < NI);

  if (tid < NI) {
    const float* row = s->ADJ + tid * LDJ;
    int c = 0;
    for (int j = 0; j < NI; j++) c += (row[j] != 0.f) ? 1 : 0;
    s->cnt[tid] = (c > 0) ? (float)c : 1.f;
  }
  load_wt(s->WT, widx_r, tid);
  __syncthreads();

  u64 acc[RI][4];
  if (act) {
    mm_zero<RI>(acc);
    mm2<RI, false>(acc, X, LDA, s->WT, LDW, i0, c0, 128);
    mm_store<RI>(acc, T1, LDA, i0, c0);
  }
  __syncthreads();
  load_wt(s->WT, widx_root, tid);
  __syncthreads();

  if (act) {
    mm_zero<RI>(acc);
    mm2<RI, true>(acc, s->ADJ, LDJ, T1, LDA, i0, c0, NI);
#pragma unroll
    for (int r = 0; r < RI; r++) {
      u64 rp = bcast2(1.f / s->cnt[i0 + r]);
#pragma unroll
      for (int j = 0; j < 4; j++) acc[r][j] = fmul2(acc[r][j], rp);
    }
    mm2<RI, false>(acc, X, LDA, s->WT, LDW, i0, c0, 128);
    float4 b1 = *reinterpret_cast<const float4*>(br + c0);
    float4 b2 = *reinterpret_cast<const float4*>(br + c0 + 64);
    mm_epi_store<RI, true>(acc, b1, b2, T2, LDA, i0, c0);
  }
  __syncthreads();

  *Xp = T2; *T2p = X;   // features now in T2; old X becomes scratch
}

template<int NI>
__device__ void mean_pool(Smem* s, const float* X, int stage, int tid) {
  const int q = tid >> 7, h = tid & 127;
  float a = 0.f;
  for (int r = q; r < NI; r += 4) a += X[r * LDA + h];
  s->part[q * 128 + h] = a;
  __syncthreads();
  if (tid < 128)
    s->xsum[stage * 128 + tid] =
        (s->part[tid] + s->part[128 + tid] + s->part[256 + tid] + s->part[384 + tid])
        * (1.f / (float)NI);
  __syncthreads();
}

// ---------------------------------------------------------------------------
// ASAP pool
// ---------------------------------------------------------------------------
template<int NI, int KK>
__device__ void asap_pool(Smem* s, float** Xp, float** T1p, float** T2p,
    int widx_lin,
    const float* __restrict__ lb,
    const float* __restrict__ aw,  const float* __restrict__ abp,
    const float* __restrict__ l1w, const float* __restrict__ l1bp,
    const float* __restrict__ l2w,
    const float* __restrict__ l3w, const float* __restrict__ l3bp,
    int tid)
{
  float* X  = *Xp;
  float* T1 = *T1p;
  float* T2 = *T2p;
  constexpr int RI = (NI == 64) ? 2 : 1;
  const int ti = tid >> 4, th = tid & 15, c0 = th * 4;
  const int i0 = (NI == 64) ? ti * 2 : ti;
  const bool act = (NI == 64) || (ti < NI);
  const int w = tid >> 5, lane = tid & 31;
  const float ab = abp[0];

  // 1. adj1 diagonal fix
  if (tid < NI) {
    float d = s->ADJ[tid * LDJ + tid];
    if (d == 0.f) s->ADJ[tid * LDJ + tid] = 1.f;
  }
  __syncthreads();

  // 2. degw (warp row-sums) + masked max-agg -> T1 ; stage lw^T
  for (int d = w; d < NI; d += 16) {
    float a = 0.f;
    for (int j = lane; j < NI; j += 32) a += s->ADJ[d * LDJ + j];
    a = warp_red_sum(a);
    if (lane == 0) s->degw[d] = a;
  }
  if (act) {
    float mac[RI][8];
    mm_maxagg<RI>(mac, s->ADJ, X, i0, c0, NI);
#pragma unroll
    for (int r = 0; r < RI; r++) {
      *reinterpret_cast<float4*>(T1 + (i0 + r) * LDA + c0) =
          make_float4(mac[r][0], mac[r][1], mac[r][2], mac[r][3]);
      *reinterpret_cast<float4*>(T1 + (i0 + r) * LDA + c0 + 64) =
          make_float4(mac[r][4], mac[r][5], mac[r][6], mac[r][7]);
    }
  }
  load_wt(s->WT, widx_lin, tid);
  __syncthreads();

  // 3. XQ = T1 @ lw^T + lb -> T2
  if (act) {
    u64 acc[RI][4];
    mm_zero<RI>(acc);
    mm2<RI, false>(acc, T1, LDA, s->WT, LDW, i0, c0, 128);
    float4 b1 = *reinterpret_cast<const float4*>(lb + c0);
    float4 b2 = *reinterpret_cast<const float4*>(lb + c0 + 64);
    mm_epi_store<RI, false>(acc, b1, b2, T2, LDA, i0, c0);
  }
  __syncthreads();

  // 4. s1 = XQ . aw[:128], s2 = X . aw[128:]  (warp dots)
  for (int d = w; d < 2 * NI; d += 16) {
    const float* row = (d < NI) ? (T2 + d * LDA) : (X + (d - NI) * LDA);
    const float* wv  = (d < NI) ? aw : (aw + 128);
    float4 a = reinterpret_cast<const float4*>(row)[lane];
    float4 b = reinterpret_cast<const float4*>(wv)[lane];
    float dot = a.x * b.x + a.y * b.y + a.z * b.z + a.w * b.w;
    dot = warp_red_sum(dot);
    if (lane == 0) { if (d < NI) s->s1[d] = dot; else s->s2[d - NI] = dot; }
  }
  __syncthreads();

  // 5. masked softmax attention -> S
  {
    constexpr int NCH = (NI + 31) / 32;
    for (int i = w; i < NI; i += 16) {
      float s1i = s->s1[i];
      float ev[NCH];
      float mx = -1e30f;
#pragma unroll
      for (int c = 0; c < NCH; c++) {
        int j = c * 32 + lane;
        float adjv = (j < NI) ? s->ADJ[i * LDJ + j] : 0.f;
        float e = s1i + ((j < NI) ? s->s2[j] : 0.f) + ab;
        e = (e > 0.f) ? e : SLOPE * e;
        ev[c] = (adjv != 0.f) ? e : -1e30f;
        mx = fmaxf(mx, ev[c]);
      }
#pragma unroll
      for (int o = 16; o; o >>= 1) mx = fmaxf(mx, __shfl_xor_sync(0xffffffffu, mx, o));
      float sum = 0.f, ex[NCH];
#pragma unroll
      for (int c = 0; c < NCH; c++) {
        ex[c] = (ev[c] > -5e29f) ? __expf(ev[c] - mx) : 0.f;
        sum += ex[c];
      }
      sum = warp_red_sum(sum);
      float inv = 1.f / sum;
#pragma unroll
      for (int c = 0; c < NCH; c++) {
        int j = c * 32 + lane;
        if (j < NI) s->S[i * LDJ + j] = ex[c] * inv;
      }
    }
  }
  __syncthreads();

  // 6. XC = S @ X -> T1
  if (act) {
    u64 acc[RI][4];
    mm_zero<RI>(acc);
    mm2<RI, true>(acc, s->S, LDJ, X, LDA, i0, c0, NI);
    mm_store<RI>(acc, T1, LDA, i0, c0);
  }
  __syncthreads();

  // 7. av/bv/cv: three 128-dots per row of XC
  for (int d = w; d < 3 * NI; d += 16) {
    int grp = d / NI, i = d - grp * NI;
    const float* wv = (grp == 0) ? l1w : (grp == 1) ? l2w : l3w;
    float4 a = reinterpret_cast<const float4*>(T1 + i * LDA)[lane];
    float4 b = reinterpret_cast<const float4*>(wv)[lane];
    float dot = a.x * b.x + a.y * b.y + a.z * b.z + a.w * b.w;
    dot = warp_red_sum(dot);
    if (lane == 0) {
      if (grp == 0)      s->av[i] = dot + l1bp[0];
      else if (grp == 1) s->bv[i] = dot;
      else               s->cv[i] = dot + l3bp[0];
    }
  }
  __syncthreads();

  // 8. fit = sigmoid( adj1 @ av - bv*degw + cv )
  for (int d = w; d < NI; d += 16) {
    float a = 0.f;
    for (int j = lane; j < NI; j += 32) a += s->ADJ[d * LDJ + j] * s->av[j];
    a = warp_red_sum(a);
    if (lane == 0) {
      float f = a - s->bv[d] * s->degw[d] + s->cv[d];
      s->fit[d] = 1.f / (1.f + expf(-f));
    }
  }
  __syncthreads();

  // 9. top-k via warp argmax (warp 0); ties -> lowest index (matches top_k)
  if (tid < 32) {
    float v0 = (lane < NI) ? s->fit[lane] : -2.f;
    float v1 = (lane + 32 < NI) ? s->fit[lane + 32] : -2.f;
#pragma unroll 1
    for (int t = 0; t < KK; t++) {
      float bv; int bi;
      if (v0 >= v1) { bv = v0; bi = lane; } else { bv = v1; bi = lane + 32; }
#pragma unroll
      for (int o = 16; o; o >>= 1) {
        float ov = __shfl_xor_sync(0xffffffffu, bv, o);
        int   oi = __shfl_xor_sync(0xffffffffu, bi, o);
        if (ov > bv || (ov == bv && oi < bi)) { bv = ov; bi = oi; }
      }
      if (lane == 0) { s->perm[t] = bi; s->vals[t] = bv; }
      if (bi == lane) v0 = -2.f;
      if (bi == lane + 32) v1 = -2.f;
    }
  }
  __syncthreads();

  // 10. XN = XC[perm]*vals -> T2 ; Tb = S[perm] @ ADJ -> X (scratch)
  for (int idx = tid; idx < KK * 128; idx += THREADS) {
    int t = idx >> 7, h = idx & 127;
    T2[t * LDA + h] = T1[s->perm[t] * LDA + h] * s->vals[t];
  }
  for (int idx = tid; idx < KK * NI; idx += THREADS) {
    int t = idx / NI, m = idx - t * NI;
    const float* srow = s->S + s->perm[t] * LDJ;
    float a = 0.f;
    for (int n = 0; n < NI; n++) {
      float sv = srow[n];
      if (sv != 0.f) a += sv * s->ADJ[n * LDJ + m];
    }
    X[t * LDA + m] = a;
  }
  __syncthreads();

  // 11. adjn = Tb @ S[perm]^T, zero diagonal
  for (int idx = tid; idx < KK * KK; idx += THREADS) {
    int t = idx / KK, l = idx - t * KK;
    const float* sl = s->S + s->perm[l] * LDJ;
    const float* tr = X + t * LDA;
    float a = 0.f;
    for (int m = 0; m < NI; m++) a += tr[m] * sl[m];
    s->adjn[t * KK + l] = (t == l) ? 0.f : a;
  }
  __syncthreads();
  for (int idx = tid; idx < KK * KK; idx += THREADS) {
    int t = idx / KK, l = idx - t * KK;
    s->ADJ[t * LDJ + l] = s->adjn[t * KK + l];
  }
  __syncthreads();

  *Xp = T2; *T2p = X;
}

// ---------------------------------------------------------------------------
// main kernel
// ---------------------------------------------------------------------------
__global__ void __launch_bounds__(THREADS, 1) asap_kernel(
    const float* __restrict__ x,          const float* __restrict__ adj,
    const float* __restrict__ conv1_br,
    const float* __restrict__ convs_br,
    const float* __restrict__ pool_lin_b,
    const float* __restrict__ pool_att_w, const float* __restrict__ pool_att_b,
    const float* __restrict__ pool_le1_w, const float* __restrict__ pool_le1_b,
    const float* __restrict__ pool_le2_w,
    const float* __restrict__ pool_le3_w, const float* __restrict__ pool_le3_b,
    const float* __restrict__ lin1_w,     const float* __restrict__ lin1_b,
    const float* __restrict__ lin2_w,     const float* __restrict__ lin2_b,
    float* __restrict__ out)
{
  extern __shared__ unsigned char smraw[];
  Smem* s = reinterpret_cast<Smem*>(smraw);
  const int g = blockIdx.x, tid = threadIdx.x;
  const int w = tid >> 5, lane = tid & 31;

  // load features + adjacency (float4)
  {
    const float4* xs = reinterpret_cast<const float4*>(x + g * (64 * 128));
    float4* xd = reinterpret_cast<float4*>(s->A);
#pragma unroll
    for (int i = 0; i < 4; i++) xd[tid + i * 512] = xs[tid + i * 512];
    const float4* as = reinterpret_cast<const float4*>(adj + g * (64 * 64));
    for (int idx = tid; idx < 64 * 16; idx += THREADS) {
      int row = idx >> 4, c = idx & 15;
      *reinterpret_cast<float4*>(s->ADJ + row * LDJ + c * 4) = as[idx];
    }
  }
  __syncthreads();

  float* X  = s->A;
  float* T1 = s->B;
  float* T2 = s->Cb;

  graph_conv<64>(s, &X, &T1, &T2, 0, 1, conv1_br, tid);
  mean_pool<64>(s, X, 0, tid);

  graph_conv<64>(s, &X, &T1, &T2, 2, 6, convs_br, tid);
  mean_pool<64>(s, X, 1, tid);
  asap_pool<64, 16>(s, &X, &T1, &T2, 10,
      pool_lin_b, pool_att_w, pool_att_b,
      pool_le1_w, pool_le1_b, pool_le2_w, pool_le3_w, pool_le3_b, tid);

  graph_conv<16>(s, &X, &T1, &T2, 3, 7, convs_br + 128, tid);
  mean_pool<16>(s, X, 2, tid);

  graph_conv<16>(s, &X, &T1, &T2, 4, 8, convs_br + 256, tid);
  mean_pool<16>(s, X, 3, tid);
  asap_pool<16, 4>(s, &X, &T1, &T2, 11,
      pool_lin_b + 128, pool_att_w + 256, pool_att_b + 1,
      pool_le1_w + 128, pool_le1_b + 1, pool_le2_w + 128,
      pool_le3_w + 128, pool_le3_b + 1, tid);

  graph_conv<4>(s, &X, &T1, &T2, 5, 9, convs_br + 384, tid);
  mean_pool<4>(s, X, 4, tid);

  // MLP head: zz = relu( xsum(640) @ lin1_w^T + lin1_b )   (warp dots)
  for (int d = w; d < 128; d += 16) {
    const float4* zr = reinterpret_cast<const float4*>(s->xsum);
    const float4* wr = reinterpret_cast<const float4*>(lin1_w + d * 640);
    float a = 0.f;
#pragma unroll
    for (int c = 0; c < 5; c++) {
      float4 zc = zr[lane + 32 * c];
      float4 wc = wr[lane + 32 * c];
      a += zc.x * wc.x + zc.y * wc.y + zc.z * wc.z + zc.w * wc.w;
    }
    a = warp_red_sum(a);
    if (lane == 0) s->zz[d] = fmaxf(a + lin1_b[d], 0.f);
  }
  __syncthreads();
  for (int d = w; d < 10; d += 16) {
    float4 zc = reinterpret_cast<const float4*>(s->zz)[lane];
    float4 wc = reinterpret_cast<const float4*>(lin2_w + d * 128)[lane];
    float a = zc.x * wc.x + zc.y * wc.y + zc.z * wc.z + zc.w * wc.w;
    a = warp_red_sum(a);
    if (lane == 0) s->yy[d] = a + lin2_b[d];
  }
  __syncthreads();
  if (tid == 0) {
    float mx = -1e30f;
    for (int c = 0; c < 10; c++) mx = fmaxf(mx, s->yy[c]);
    float sum = 0.f;
    for (int c = 0; c < 10; c++) sum += expf(s->yy[c] - mx);
    s->lse = mx + logf(sum);
  }
  __syncthreads();
  if (tid < 10) out[g * 10 + tid] = s->yy[tid] - s->lse;
}

// ---------------------------------------------------------------------------
// prologue: transpose the 12 [128x128] weight matrices into g_WT
// ---------------------------------------------------------------------------
__global__ void transpose_k(
    const float* __restrict__ conv1_wr, const float* __restrict__ conv1_wroot,
    const float* __restrict__ convs_wr, const float* __restrict__ convs_wroot,
    const float* __restrict__ pool_lin_w)
{
  __shared__ float t[32][33];
  int mat = blockIdx.y;
  int tile = blockIdx.x;
  int tx = tile & 3, ty = tile >> 2;
  const float* src =
      (mat == 0) ? conv1_wr :
      (mat == 1) ? conv1_wroot :
      (mat < 6)  ? convs_wr + (mat - 2) * 16384 :
      (mat < 10) ? convs_wroot + (mat - 6) * 16384 :
                   pool_lin_w + (mat - 10) * 16384;
#pragma unroll
  for (int r = threadIdx.y; r < 32; r += 8)
    t[r][threadIdx.x] = src[(ty * 32 + r) * 128 + tx * 32 + threadIdx.x];
  __syncthreads();
#pragma unroll
  for (int r = threadIdx.y; r < 32; r += 8)
    g_WT[mat * 16384 + (tx * 32 + r) * 128 + ty * 32 + threadIdx.x] = t[threadIdx.x][r];
}

// ---------------------------------------------------------------------------
// launch
// ---------------------------------------------------------------------------
extern "C" void kernel_launch(void* const* d_in, const int* in_sizes, int n_in,
                              void* d_out, int out_size)
{
  const float* x           = (const float*)d_in[0];
  const float* adj         = (const float*)d_in[1];
  const float* conv1_wr    = (const float*)d_in[2];
  const float* conv1_br    = (const float*)d_in[3];
  const float* conv1_wroot = (const float*)d_in[4];
  const float* convs_wr    = (const float*)d_in[5];
  const float* convs_br    = (const float*)d_in[6];
  const float* convs_wroot = (const float*)d_in[7];
  const float* pool_lin_w  = (const float*)d_in[8];
  const float* pool_lin_b  = (const float*)d_in[9];
  const float* pool_att_w  = (const float*)d_in[10];
  const float* pool_att_b  = (const float*)d_in[11];
  const float* pool_le1_w  = (const float*)d_in[12];
  const float* pool_le1_b  = (const float*)d_in[13];
  const float* pool_le2_w  = (const float*)d_in[14];
  const float* pool_le3_w  = (const float*)d_in[15];
  const float* pool_le3_b  = (const float*)d_in[16];
  const float* lin1_w      = (const float*)d_in[17];
  const float* lin1_b      = (const float*)d_in[18];
  const float* lin2_w      = (const float*)d_in[19];
  const float* lin2_b      = (const float*)d_in[20];
  float* out = (float*)d_out;

  transpose_k<<<dim3(16, 12), dim3(32, 8)>>>(
      conv1_wr, conv1_wroot, convs_wr, convs_wroot, pool_lin_w);

  cudaFuncSetAttribute(asap_kernel, cudaFuncAttributeMaxDynamicSharedMemorySize,
                       (int)sizeof(Smem));
  asap_kernel<<<G_TOT, THREADS, sizeof(Smem)>>>(
      x, adj, conv1_br, convs_br,
      pool_lin_b, pool_att_w, pool_att_b,
      pool_le1_w, pool_le1_b, pool_le2_w, pool_le3_w, pool_le3_b,
      lin1_w, lin1_b, lin2_w, lin2_b, out);
}